// round 1
// baseline (speedup 1.0000x reference)
#include <cuda_runtime.h>
#include <cuda_bf16.h>
#include <cstdint>

#define BDIM 16
#define SDIM 2048
#define DDIM 512

// Scratch (device globals: allocation-free per harness rules). 2 x 67MB.
__device__ float g_qbuf[(size_t)BDIM * SDIM * DDIM];
__device__ float g_kbuf[(size_t)BDIM * SDIM * DDIM];

#define SM_PAD 40  // 32 bf16 payload + 8 pad -> conflict-free fragment LDS

__device__ __forceinline__ void cvt2(float x, float y, __nv_bfloat16* hp, __nv_bfloat16* lp) {
    __nv_bfloat162 h, l;
    h.x = __float2bfloat16(x);
    h.y = __float2bfloat16(y);
    l.x = __float2bfloat16(x - __bfloat162float(h.x));
    l.y = __float2bfloat16(y - __bfloat162float(h.y));
    *reinterpret_cast<__nv_bfloat162*>(hp) = h;
    *reinterpret_cast<__nv_bfloat162*>(lp) = l;
}

// Load 128 rows x 32 cols fp32 (row stride ld), split to hi/lo bf16 smem [128][SM_PAD]
__device__ __forceinline__ void load_km(const float* __restrict__ src, int ld,
                                        __nv_bfloat16* sh, __nv_bfloat16* sl, int tid) {
#pragma unroll
    for (int i = 0; i < 4; i++) {
        int idx = tid + i * 256;
        int r = idx >> 3;
        int c4 = (idx & 7) * 4;
        const float4 v = *reinterpret_cast<const float4*>(src + (size_t)r * ld + c4);
        cvt2(v.x, v.y, sh + r * SM_PAD + c4, sl + r * SM_PAD + c4);
        cvt2(v.z, v.w, sh + r * SM_PAD + c4 + 2, sl + r * SM_PAD + c4 + 2);
    }
}

// Load 32 rows(k) x 128 cols(n) fp32 (row stride ld), store TRANSPOSED hi/lo smem [n][SM_PAD]
__device__ __forceinline__ void load_tr(const float* __restrict__ src, int ld,
                                        __nv_bfloat16* sh, __nv_bfloat16* sl, int tid) {
#pragma unroll
    for (int i = 0; i < 4; i++) {
        int idx = tid + i * 256;
        int kr = idx >> 5;
        int c4 = (idx & 31) * 4;
        const float4 v = *reinterpret_cast<const float4*>(src + (size_t)kr * ld + c4);
        float vv[4] = {v.x, v.y, v.z, v.w};
#pragma unroll
        for (int j = 0; j < 4; j++) {
            __nv_bfloat16 h = __float2bfloat16(vv[j]);
            sh[(c4 + j) * SM_PAD + kr] = h;
            sl[(c4 + j) * SM_PAD + kr] = __float2bfloat16(vv[j] - __bfloat162float(h));
        }
    }
}

#define MMA(d, a, b)                                                       \
    asm volatile(                                                          \
        "mma.sync.aligned.m16n8k16.row.col.f32.bf16.bf16.f32 "             \
        "{%0,%1,%2,%3},{%4,%5,%6,%7},{%8,%9},{%0,%1,%2,%3};\n"             \
        : "+f"((d)[0]), "+f"((d)[1]), "+f"((d)[2]), "+f"((d)[3])           \
        : "r"((a)[0]), "r"((a)[1]), "r"((a)[2]), "r"((a)[3]),              \
          "r"((b)[0]), "r"((b)[1]))

__device__ __forceinline__ uint32_t lds32(const __nv_bfloat16* p) {
    return *reinterpret_cast<const uint32_t*>(p);
}

// One bf16 pass over a 128x128x32 tile: C += A * B^T (A [m][k], B [n][k] in smem)
__device__ __forceinline__ void mma_pass(const __nv_bfloat16* As, const __nv_bfloat16* Bs,
                                         float acc[4][4][4], int lane, int wm, int wn) {
    const int g = lane >> 2, tg = lane & 3;
#pragma unroll
    for (int ks = 0; ks < 32; ks += 16) {
        uint32_t a[4][4], bfr[4][2];
#pragma unroll
        for (int mi = 0; mi < 4; mi++) {
            int r = wm * 64 + mi * 16 + g;
            int c = ks + tg * 2;
            a[mi][0] = lds32(As + r * SM_PAD + c);
            a[mi][1] = lds32(As + (r + 8) * SM_PAD + c);
            a[mi][2] = lds32(As + r * SM_PAD + c + 8);
            a[mi][3] = lds32(As + (r + 8) * SM_PAD + c + 8);
        }
#pragma unroll
        for (int ni = 0; ni < 4; ni++) {
            int n = wn * 32 + ni * 8 + g;
            bfr[ni][0] = lds32(Bs + n * SM_PAD + ks + tg * 2);
            bfr[ni][1] = lds32(Bs + n * SM_PAD + ks + tg * 2 + 8);
        }
#pragma unroll
        for (int mi = 0; mi < 4; mi++)
#pragma unroll
            for (int ni = 0; ni < 4; ni++)
                MMA(acc[mi][ni], a[mi], bfr[ni]);
    }
}

// ---------------- Kernel 1: projections q = X@Wq^T + bq, k = X@Wk^T + bk ----------------
__global__ void __launch_bounds__(256) proj_kernel(
    const float* __restrict__ query, const float* __restrict__ key,
    const float* __restrict__ Wq, const float* __restrict__ bq,
    const float* __restrict__ Wk, const float* __restrict__ bk) {
    __shared__ __nv_bfloat16 Ash[128 * SM_PAD], Asl[128 * SM_PAD];
    __shared__ __nv_bfloat16 Bsh[128 * SM_PAD], Bsl[128 * SM_PAD];

    const int z = blockIdx.z;
    const float* X = z ? key : query;
    const float* W = z ? Wk : Wq;
    const float* bias = z ? bk : bq;
    float* out = z ? g_kbuf : g_qbuf;

    const int col0 = blockIdx.x * 128;
    const int row0 = blockIdx.y * 128;
    const int tid = threadIdx.x, lane = tid & 31, wid = tid >> 5;
    const int wm = wid & 1, wn = wid >> 1;

    float acc[4][4][4];
#pragma unroll
    for (int i = 0; i < 4; i++)
#pragma unroll
        for (int j = 0; j < 4; j++)
#pragma unroll
            for (int c = 0; c < 4; c++) acc[i][j][c] = 0.f;

    for (int k0 = 0; k0 < DDIM; k0 += 32) {
        load_km(X + (size_t)row0 * DDIM + k0, DDIM, Ash, Asl, tid);
        load_km(W + (size_t)col0 * DDIM + k0, DDIM, Bsh, Bsl, tid);
        __syncthreads();
        mma_pass(Ash, Bsh, acc, lane, wm, wn);
        mma_pass(Ash, Bsl, acc, lane, wm, wn);
        mma_pass(Asl, Bsh, acc, lane, wm, wn);
        __syncthreads();
    }

    const int g = lane >> 2, tg = lane & 3;
#pragma unroll
    for (int mi = 0; mi < 4; mi++) {
#pragma unroll
        for (int ni = 0; ni < 4; ni++) {
            int r = row0 + wm * 64 + mi * 16 + g;
            int c = col0 + wn * 32 + ni * 8 + tg * 2;
            float b0 = bias[c], b1 = bias[c + 1];
            float2 s0 = make_float2(acc[mi][ni][0] + b0, acc[mi][ni][1] + b1);
            float2 s1 = make_float2(acc[mi][ni][2] + b0, acc[mi][ni][3] + b1);
            *reinterpret_cast<float2*>(&out[(size_t)r * DDIM + c]) = s0;
            *reinterpret_cast<float2*>(&out[(size_t)(r + 8) * DDIM + c]) = s1;
        }
    }
}

// ---------------- Kernel 2: raw scores = bias + q @ k^T ----------------
__global__ void __launch_bounds__(256) scores_kernel(
    const float* __restrict__ attn_bias, float* __restrict__ attn) {
    __shared__ __nv_bfloat16 Ash[128 * SM_PAD], Asl[128 * SM_PAD];
    __shared__ __nv_bfloat16 Bsh[128 * SM_PAD], Bsl[128 * SM_PAD];

    const int kt = blockIdx.x, qt = blockIdx.y, b = blockIdx.z;
    const float* A = g_qbuf + ((size_t)b * SDIM + qt * 128) * DDIM;
    const float* Bm = g_kbuf + ((size_t)b * SDIM + kt * 128) * DDIM;

    const int tid = threadIdx.x, lane = tid & 31, wid = tid >> 5;
    const int wm = wid & 1, wn = wid >> 1;

    float acc[4][4][4];
#pragma unroll
    for (int i = 0; i < 4; i++)
#pragma unroll
        for (int j = 0; j < 4; j++)
#pragma unroll
            for (int c = 0; c < 4; c++) acc[i][j][c] = 0.f;

    for (int k0 = 0; k0 < DDIM; k0 += 32) {
        load_km(A + k0, DDIM, Ash, Asl, tid);
        load_km(Bm + k0, DDIM, Bsh, Bsl, tid);
        __syncthreads();
        mma_pass(Ash, Bsh, acc, lane, wm, wn);
        mma_pass(Ash, Bsl, acc, lane, wm, wn);
        mma_pass(Asl, Bsh, acc, lane, wm, wn);
        __syncthreads();
    }

    float* aout = attn + (size_t)b * SDIM * SDIM;
    const int g = lane >> 2, tg = lane & 3;
#pragma unroll
    for (int mi = 0; mi < 4; mi++) {
#pragma unroll
        for (int ni = 0; ni < 4; ni++) {
            int qr = qt * 128 + wm * 64 + mi * 16 + g;
            int kc = kt * 128 + wn * 32 + ni * 8 + tg * 2;
            float2 bv0 = *reinterpret_cast<const float2*>(&attn_bias[(size_t)qr * SDIM + kc]);
            float2 bv1 = *reinterpret_cast<const float2*>(&attn_bias[(size_t)(qr + 8) * SDIM + kc]);
            float2 s0 = make_float2(acc[mi][ni][0] + bv0.x, acc[mi][ni][1] + bv0.y);
            float2 s1 = make_float2(acc[mi][ni][2] + bv1.x, acc[mi][ni][3] + bv1.y);
            *reinterpret_cast<float2*>(&aout[(size_t)qr * SDIM + kc]) = s0;
            *reinterpret_cast<float2*>(&aout[(size_t)(qr + 8) * SDIM + kc]) = s1;
        }
    }
}

// ---------------- Kernel 3: per-row softmax, in place ----------------
__global__ void __launch_bounds__(256) softmax_kernel(float* __restrict__ attn) {
    __shared__ float red[8];
    const int tid = threadIdx.x, lane = tid & 31, wid = tid >> 5;
    float4* row = reinterpret_cast<float4*>(
        attn + ((size_t)blockIdx.y * SDIM + blockIdx.x) * SDIM);

    float4 v0 = row[tid];
    float4 v1 = row[tid + 256];

    float m = fmaxf(fmaxf(fmaxf(v0.x, v0.y), fmaxf(v0.z, v0.w)),
                    fmaxf(fmaxf(v1.x, v1.y), fmaxf(v1.z, v1.w)));
#pragma unroll
    for (int o = 16; o; o >>= 1) m = fmaxf(m, __shfl_xor_sync(0xFFFFFFFFu, m, o));
    if (lane == 0) red[wid] = m;
    __syncthreads();
    if (tid == 0) {
        float mm = red[0];
#pragma unroll
        for (int i = 1; i < 8; i++) mm = fmaxf(mm, red[i]);
        red[0] = mm;
    }
    __syncthreads();
    m = red[0];
    __syncthreads();

    float e[8];
    e[0] = __expf(v0.x - m); e[1] = __expf(v0.y - m);
    e[2] = __expf(v0.z - m); e[3] = __expf(v0.w - m);
    e[4] = __expf(v1.x - m); e[5] = __expf(v1.y - m);
    e[6] = __expf(v1.z - m); e[7] = __expf(v1.w - m);

    float s = 0.f;
#pragma unroll
    for (int i = 0; i < 8; i++) s += e[i];
#pragma unroll
    for (int o = 16; o; o >>= 1) s += __shfl_xor_sync(0xFFFFFFFFu, s, o);
    if (lane == 0) red[wid] = s;
    __syncthreads();
    if (tid == 0) {
        float ss = 0.f;
#pragma unroll
        for (int i = 0; i < 8; i++) ss += red[i];
        red[0] = ss;
    }
    __syncthreads();
    float inv = 1.0f / red[0];

    row[tid] = make_float4(e[0] * inv, e[1] * inv, e[2] * inv, e[3] * inv);
    row[tid + 256] = make_float4(e[4] * inv, e[5] * inv, e[6] * inv, e[7] * inv);
}

// ---------------- Kernel 4: out = attention @ value ----------------
__global__ void __launch_bounds__(256) pv_kernel(
    const float* __restrict__ value, const float* __restrict__ attn,
    float* __restrict__ out) {
    __shared__ __nv_bfloat16 Ash[128 * SM_PAD], Asl[128 * SM_PAD];
    __shared__ __nv_bfloat16 Bsh[128 * SM_PAD], Bsl[128 * SM_PAD];

    const int dt = blockIdx.x, qt = blockIdx.y, b = blockIdx.z;
    const float* A = attn + (size_t)b * SDIM * SDIM + (size_t)qt * 128 * SDIM;
    const float* V = value + (size_t)b * SDIM * DDIM + dt * 128;

    const int tid = threadIdx.x, lane = tid & 31, wid = tid >> 5;
    const int wm = wid & 1, wn = wid >> 1;

    float acc[4][4][4];
#pragma unroll
    for (int i = 0; i < 4; i++)
#pragma unroll
        for (int j = 0; j < 4; j++)
#pragma unroll
            for (int c = 0; c < 4; c++) acc[i][j][c] = 0.f;

    for (int k0 = 0; k0 < SDIM; k0 += 32) {
        load_km(A + k0, SDIM, Ash, Asl, tid);
        load_tr(V + (size_t)k0 * DDIM, DDIM, Bsh, Bsl, tid);
        __syncthreads();
        mma_pass(Ash, Bsh, acc, lane, wm, wn);
        mma_pass(Ash, Bsl, acc, lane, wm, wn);
        mma_pass(Asl, Bsh, acc, lane, wm, wn);
        __syncthreads();
    }

    const int g = lane >> 2, tg = lane & 3;
#pragma unroll
    for (int mi = 0; mi < 4; mi++) {
#pragma unroll
        for (int ni = 0; ni < 4; ni++) {
            int r = qt * 128 + wm * 64 + mi * 16 + g;
            int c = dt * 128 + wn * 32 + ni * 8 + tg * 2;
            float2 s0 = make_float2(acc[mi][ni][0], acc[mi][ni][1]);
            float2 s1 = make_float2(acc[mi][ni][2], acc[mi][ni][3]);
            size_t base = ((size_t)b * SDIM + r) * DDIM + c;
            *reinterpret_cast<float2*>(&out[base]) = s0;
            *reinterpret_cast<float2*>(&out[base + 8 * DDIM]) = s1;
        }
    }
}

extern "C" void kernel_launch(void* const* d_in, const int* in_sizes, int n_in,
                              void* d_out, int out_size) {
    const float* query     = (const float*)d_in[0];
    const float* key       = (const float*)d_in[1];
    const float* value     = (const float*)d_in[2];
    const float* attn_bias = (const float*)d_in[3];
    const float* Wq        = (const float*)d_in[4];
    const float* bq        = (const float*)d_in[5];
    const float* Wk        = (const float*)d_in[6];
    const float* bk        = (const float*)d_in[7];

    float* out  = (float*)d_out;                            // [B,S,D]
    float* attn = out + (size_t)BDIM * SDIM * DDIM;         // [B,S,S]

    proj_kernel<<<dim3(4, 256, 2), 256>>>(query, key, Wq, bq, Wk, bk);
    scores_kernel<<<dim3(16, 16, 16), 256>>>(attn_bias, attn);
    softmax_kernel<<<dim3(SDIM, BDIM), 256>>>(attn);
    pv_kernel<<<dim3(4, 16, 16), 256>>>(value, attn, out);
}

// round 4
// speedup vs baseline: 1.4843x; 1.4843x over previous
#include <cuda_runtime.h>
#include <cuda_bf16.h>
#include <cstdint>

#define BDIM 16
#define SDIM 2048
#define DDIM 512

#define SZ_BSD ((size_t)BDIM * SDIM * DDIM)   // 16,777,216
#define SZ_BSS ((size_t)BDIM * SDIM * SDIM)   // 67,108,864

// -------------------- device scratch (static, harness-legal) ----------------
__device__ __nv_bfloat16 g_inqh[SZ_BSD], g_inql[SZ_BSD];   // split(query)
__device__ __nv_bfloat16 g_inkh[SZ_BSD], g_inkl[SZ_BSD];   // split(key)
__device__ __nv_bfloat16 g_wh[2 * DDIM * DDIM], g_wl[2 * DDIM * DDIM]; // split(Wq|Wk)
__device__ __nv_bfloat16 g_qh[SZ_BSD], g_ql[SZ_BSD];       // split(q)
__device__ __nv_bfloat16 g_kh[SZ_BSD], g_kl[SZ_BSD];       // split(k)
__device__ __nv_bfloat16 g_vh[SZ_BSD], g_vl[SZ_BSD];       // split(V^T) [b][d][s]
__device__ __nv_bfloat16 g_ah[SZ_BSS], g_al[SZ_BSS];       // split(attention)

// -------------------- GEMM building blocks ----------------------------------
// SMEM tile: 128 rows x 32 bf16, padded row stride 40 elems (80B).
// 80B stride => ldmatrix 8-row groups hit all eight 16B slots mod 128 (no conflicts).
#define ROWB 80
#define BUFB (128 * ROWB)        // 10240 B per half-tensor tile
#define STAGEB (4 * BUFB)        // Ah, Al, Bh, Bl
#define GEMM_SMEM_BYTES (2 * STAGEB)  // 81920

__device__ __forceinline__ uint32_t smem_u32(const void* p) {
    return (uint32_t)__cvta_generic_to_shared(p);
}

__device__ __forceinline__ void cp16(uint32_t dst, const void* src) {
    asm volatile("cp.async.cg.shared.global [%0], [%1], 16;" :: "r"(dst), "l"(src));
}
__device__ __forceinline__ void cp_commit() {
    asm volatile("cp.async.commit_group;");
}
template <int N>
__device__ __forceinline__ void cp_wait() {
    asm volatile("cp.async.wait_group %0;" :: "n"(N));
}

__device__ __forceinline__ void ldsm4(uint32_t* r, uint32_t addr) {
    asm volatile("ldmatrix.sync.aligned.m8n8.x4.shared.b16 {%0,%1,%2,%3}, [%4];"
                 : "=r"(r[0]), "=r"(r[1]), "=r"(r[2]), "=r"(r[3]) : "r"(addr));
}

#define MMA(d, a, b)                                                       \
    asm volatile(                                                          \
        "mma.sync.aligned.m16n8k16.row.col.f32.bf16.bf16.f32 "             \
        "{%0,%1,%2,%3},{%4,%5,%6,%7},{%8,%9},{%0,%1,%2,%3};\n"             \
        : "+f"((d)[0]), "+f"((d)[1]), "+f"((d)[2]), "+f"((d)[3])           \
        : "r"((a)[0]), "r"((a)[1]), "r"((a)[2]), "r"((a)[3]),              \
          "r"((b)[0]), "r"((b)[1]))

// Issue cp.async for one stage: {Ah, Al, Bh, Bl}, each 128 rows x 32 cols (64B).
// 2048 16B-chunks, 8 per thread.
__device__ __forceinline__ void issue_stage(
    const __nv_bfloat16* __restrict__ Ah, const __nv_bfloat16* __restrict__ Al, int lda,
    const __nv_bfloat16* __restrict__ Bh, const __nv_bfloat16* __restrict__ Bl, int ldb,
    int k0, uint32_t sstage, int tid) {
    const __nv_bfloat16* srcs[4] = {Ah, Al, Bh, Bl};
    const int lds[4] = {lda, lda, ldb, ldb};
#pragma unroll
    for (int i = 0; i < 8; i++) {
        const int id = tid + i * 256;
        const int buf = id >> 9;
        const int r = (id >> 2) & 127;
        const int c = id & 3;
        cp16(sstage + buf * BUFB + r * ROWB + c * 16,
             srcs[buf] + (size_t)r * lds[buf] + k0 + c * 8);
    }
    cp_commit();
}

// Compute 3-pass (AhBh + AhBl + AlBh) over one 128x128x32 smem stage.
__device__ __forceinline__ void compute_stage(uint32_t sstage, float acc[4][4][4],
                                              int tid) {
    const int lane = tid & 31, w = tid >> 5;
    const int wm = w & 1, wn = w >> 1;
    // A fragment base (16x16 tile): lanes 0-15 rows, lanes 16-31 k+8 chunk
    const uint32_t aoff = (uint32_t)((wm * 64 + (lane & 15)) * ROWB + ((lane >> 4) << 4));
    // B fragment base (16n x 16k): lanes %8 -> n row, bit4 -> n+8, bit3 -> k+8
    const uint32_t boff = (uint32_t)((wn * 32 + ((lane >> 4) & 1) * 8 + (lane & 7)) * ROWB +
                                     (((lane >> 3) & 1) << 4));
    const uint32_t aH = sstage + aoff, aL = sstage + BUFB + aoff;
    const uint32_t bH = sstage + 2 * BUFB + boff, bL = sstage + 3 * BUFB + boff;

#pragma unroll
    for (int ks = 0; ks < 2; ks++) {           // two k16 halves (byte offset 32)
        const uint32_t k2 = ks * 32;
        uint32_t ah[4][4], al[4][4], bh[2][4], bl[2][4];
#pragma unroll
        for (int mi = 0; mi < 4; mi++) ldsm4(ah[mi], aH + mi * 16 * ROWB + k2);
#pragma unroll
        for (int bi = 0; bi < 2; bi++) ldsm4(bh[bi], bH + bi * 16 * ROWB + k2);
#pragma unroll
        for (int mi = 0; mi < 4; mi++)
#pragma unroll
            for (int ni = 0; ni < 4; ni++)
                MMA(acc[mi][ni], ah[mi], &bh[ni >> 1][(ni & 1) * 2]);
#pragma unroll
        for (int bi = 0; bi < 2; bi++) ldsm4(bl[bi], bL + bi * 16 * ROWB + k2);
#pragma unroll
        for (int mi = 0; mi < 4; mi++)
#pragma unroll
            for (int ni = 0; ni < 4; ni++)
                MMA(acc[mi][ni], ah[mi], &bl[ni >> 1][(ni & 1) * 2]);
#pragma unroll
        for (int mi = 0; mi < 4; mi++) ldsm4(al[mi], aL + mi * 16 * ROWB + k2);
#pragma unroll
        for (int mi = 0; mi < 4; mi++)
#pragma unroll
            for (int ni = 0; ni < 4; ni++)
                MMA(acc[mi][ni], al[mi], &bh[ni >> 1][(ni & 1) * 2]);
    }
}

// Full 128x128 GEMM mainloop over K = KT*32, double-buffered cp.async.
__device__ __forceinline__ void gemm_main(
    const __nv_bfloat16* __restrict__ Ah, const __nv_bfloat16* __restrict__ Al, int lda,
    const __nv_bfloat16* __restrict__ Bh, const __nv_bfloat16* __restrict__ Bl, int ldb,
    int KT, float acc[4][4][4]) {
    extern __shared__ char smem[];
    const int tid = threadIdx.x;
    const uint32_t sb = smem_u32(smem);

#pragma unroll
    for (int i = 0; i < 4; i++)
#pragma unroll
        for (int j = 0; j < 4; j++)
#pragma unroll
            for (int c = 0; c < 4; c++) acc[i][j][c] = 0.f;

    issue_stage(Ah, Al, lda, Bh, Bl, ldb, 0, sb, tid);

    for (int kt = 0; kt < KT; kt++) {
        if (kt + 1 < KT) {
            issue_stage(Ah, Al, lda, Bh, Bl, ldb, (kt + 1) * 32,
                        sb + ((kt + 1) & 1) * STAGEB, tid);
            cp_wait<1>();
        } else {
            cp_wait<0>();
        }
        __syncthreads();
        compute_stage(sb + (kt & 1) * STAGEB, acc, tid);
        __syncthreads();
    }
}

// -------------------- prep kernels ------------------------------------------
__global__ void __launch_bounds__(256) split_kernel(const float* __restrict__ src,
                                                    int which, int n4) {
    const int i = blockIdx.x * 256 + threadIdx.x;
    if (i >= n4) return;
    __nv_bfloat16 *h, *l;
    if (which == 0)      { h = g_inqh; l = g_inql; }
    else if (which == 1) { h = g_inkh; l = g_inkl; }
    else if (which == 2) { h = g_wh;   l = g_wl;   }
    else                 { h = g_wh + DDIM * DDIM; l = g_wl + DDIM * DDIM; }
    const float4 v = reinterpret_cast<const float4*>(src)[i];
    __nv_bfloat162 h0 = __floats2bfloat162_rn(v.x, v.y);
    __nv_bfloat162 h1 = __floats2bfloat162_rn(v.z, v.w);
    float2 f0 = __bfloat1622float2(h0), f1 = __bfloat1622float2(h1);
    __nv_bfloat162 l0 = __floats2bfloat162_rn(v.x - f0.x, v.y - f0.y);
    __nv_bfloat162 l1 = __floats2bfloat162_rn(v.z - f1.x, v.w - f1.y);
    reinterpret_cast<uint2*>(h)[i] =
        make_uint2(*reinterpret_cast<uint32_t*>(&h0), *reinterpret_cast<uint32_t*>(&h1));
    reinterpret_cast<uint2*>(l)[i] =
        make_uint2(*reinterpret_cast<uint32_t*>(&l0), *reinterpret_cast<uint32_t*>(&l1));
}

// value [b][s][d] fp32 -> g_vh/g_vl [b][d][s] bf16 hi/lo (32x32 tiles)
__global__ void __launch_bounds__(256) vsplit_kernel(const float* __restrict__ value) {
    __shared__ float t[32][33];
    const int tid = threadIdx.x;
    const int b = blockIdx.z;
    const size_t s0 = (size_t)blockIdx.x * 32;
    const size_t d0 = (size_t)blockIdx.y * 32;
    const float* src = value + ((size_t)b * SDIM + s0) * DDIM + d0;
#pragma unroll
    for (int p = 0; p < 4; p++) {
        const int idx = tid + p * 256;
        const int r = idx >> 5, c = idx & 31;
        t[r][c] = src[(size_t)r * DDIM + c];
    }
    __syncthreads();
    __nv_bfloat16* dh = g_vh + ((size_t)b * DDIM + d0) * SDIM + s0;
    __nv_bfloat16* dl = g_vl + ((size_t)b * DDIM + d0) * SDIM + s0;
#pragma unroll
    for (int p = 0; p < 4; p++) {
        const int idx = tid + p * 256;
        const int dr = idx >> 5, sc = idx & 31;
        const float x = t[sc][dr];
        const __nv_bfloat16 h = __float2bfloat16(x);
        dh[(size_t)dr * SDIM + sc] = h;
        dl[(size_t)dr * SDIM + sc] = __float2bfloat16(x - __bfloat162float(h));
    }
}

// -------------------- GEMM kernels ------------------------------------------
__global__ void __launch_bounds__(256) proj_kernel(
    const float* __restrict__ bq, const float* __restrict__ bk) {
    const int z = blockIdx.z;
    const size_t row0 = (size_t)blockIdx.y * 128;
    const int col0 = blockIdx.x * 128;
    const __nv_bfloat16* Ah = (z ? g_inkh : g_inqh) + row0 * DDIM;
    const __nv_bfloat16* Al = (z ? g_inkl : g_inql) + row0 * DDIM;
    const __nv_bfloat16* Bh = g_wh + (size_t)z * DDIM * DDIM + (size_t)col0 * DDIM;
    const __nv_bfloat16* Bl = g_wl + (size_t)z * DDIM * DDIM + (size_t)col0 * DDIM;

    float acc[4][4][4];
    gemm_main(Ah, Al, DDIM, Bh, Bl, DDIM, DDIM / 32, acc);

    const int tid = threadIdx.x, lane = tid & 31, w = tid >> 5;
    const int wm = w & 1, wn = w >> 1;
    const int g = lane >> 2, tg = lane & 3;
    const float* bias = z ? bk : bq;
    __nv_bfloat16* oh = z ? g_kh : g_qh;
    __nv_bfloat16* ol = z ? g_kl : g_ql;
#pragma unroll
    for (int mi = 0; mi < 4; mi++) {
#pragma unroll
        for (int ni = 0; ni < 4; ni++) {
            const size_t r = row0 + wm * 64 + mi * 16 + g;
            const int c = col0 + wn * 32 + ni * 8 + tg * 2;
            const float b0 = bias[c], b1 = bias[c + 1];
#pragma unroll
            for (int hh = 0; hh < 2; hh++) {
                const float x = acc[mi][ni][2 * hh]     + b0;
                const float y = acc[mi][ni][2 * hh + 1] + b1;
                __nv_bfloat162 h2 = __floats2bfloat162_rn(x, y);
                float2 hf = __bfloat1622float2(h2);
                __nv_bfloat162 l2 = __floats2bfloat162_rn(x - hf.x, y - hf.y);
                const size_t o = (r + hh * 8) * DDIM + c;
                *reinterpret_cast<uint32_t*>(oh + o) = *reinterpret_cast<uint32_t*>(&h2);
                *reinterpret_cast<uint32_t*>(ol + o) = *reinterpret_cast<uint32_t*>(&l2);
            }
        }
    }
}

__global__ void __launch_bounds__(256) scores_kernel(
    const float* __restrict__ attn_bias, float* __restrict__ attn) {
    const int kt = blockIdx.x, qt = blockIdx.y, b = blockIdx.z;
    const size_t abase = ((size_t)b * SDIM + qt * 128) * DDIM;
    const size_t bbase = ((size_t)b * SDIM + kt * 128) * DDIM;

    float acc[4][4][4];
    gemm_main(g_qh + abase, g_ql + abase, DDIM, g_kh + bbase, g_kl + bbase, DDIM,
              DDIM / 32, acc);

    const int tid = threadIdx.x, lane = tid & 31, w = tid >> 5;
    const int wm = w & 1, wn = w >> 1;
    const int g = lane >> 2, tg = lane & 3;
    float* aout = attn + (size_t)b * SDIM * SDIM;
#pragma unroll
    for (int mi = 0; mi < 4; mi++) {
#pragma unroll
        for (int ni = 0; ni < 4; ni++) {
            const size_t qr = (size_t)qt * 128 + wm * 64 + mi * 16 + g;
            const int kc = kt * 128 + wn * 32 + ni * 8 + tg * 2;
            const float2 bv0 = *reinterpret_cast<const float2*>(&attn_bias[qr * SDIM + kc]);
            const float2 bv1 = *reinterpret_cast<const float2*>(&attn_bias[(qr + 8) * SDIM + kc]);
            *reinterpret_cast<float2*>(&aout[qr * SDIM + kc]) =
                make_float2(acc[mi][ni][0] + bv0.x, acc[mi][ni][1] + bv0.y);
            *reinterpret_cast<float2*>(&aout[(qr + 8) * SDIM + kc]) =
                make_float2(acc[mi][ni][2] + bv1.x, acc[mi][ni][3] + bv1.y);
        }
    }
}

__global__ void __launch_bounds__(256) pv_kernel(float* __restrict__ out) {
    const int dt = blockIdx.x, qt = blockIdx.y, b = blockIdx.z;
    const size_t abase = (size_t)b * SDIM * SDIM + (size_t)qt * 128 * SDIM;
    const size_t bbase = ((size_t)b * DDIM + dt * 128) * SDIM;

    float acc[4][4][4];
    gemm_main(g_ah + abase, g_al + abase, SDIM, g_vh + bbase, g_vl + bbase, SDIM,
              SDIM / 32, acc);

    const int tid = threadIdx.x, lane = tid & 31, w = tid >> 5;
    const int wm = w & 1, wn = w >> 1;
    const int g = lane >> 2, tg = lane & 3;
#pragma unroll
    for (int mi = 0; mi < 4; mi++) {
#pragma unroll
        for (int ni = 0; ni < 4; ni++) {
            const size_t r = (size_t)qt * 128 + wm * 64 + mi * 16 + g;
            const int c = dt * 128 + wn * 32 + ni * 8 + tg * 2;
            const size_t base = ((size_t)b * SDIM + r) * DDIM + c;
            *reinterpret_cast<float2*>(&out[base]) =
                make_float2(acc[mi][ni][0], acc[mi][ni][1]);
            *reinterpret_cast<float2*>(&out[base + 8 * DDIM]) =
                make_float2(acc[mi][ni][2], acc[mi][ni][3]);
        }
    }
}

// -------------------- softmax (in-place) + bf16 hi/lo split write -----------
__global__ void __launch_bounds__(256) softmax_kernel(float* __restrict__ attn) {
    __shared__ float red[8];
    const int tid = threadIdx.x, lane = tid & 31, wid = tid >> 5;
    const size_t rb = ((size_t)blockIdx.y * SDIM + blockIdx.x) * SDIM;
    float4* row = reinterpret_cast<float4*>(attn + rb);

    const float4 v0 = row[tid];
    const float4 v1 = row[tid + 256];

    float m = fmaxf(fmaxf(fmaxf(v0.x, v0.y), fmaxf(v0.z, v0.w)),
                    fmaxf(fmaxf(v1.x, v1.y), fmaxf(v1.z, v1.w)));
#pragma unroll
    for (int o = 16; o; o >>= 1) m = fmaxf(m, __shfl_xor_sync(0xFFFFFFFFu, m, o));
    if (lane == 0) red[wid] = m;
    __syncthreads();
    if (tid == 0) {
        float mm = red[0];
#pragma unroll
        for (int i = 1; i < 8; i++) mm = fmaxf(mm, red[i]);
        red[0] = mm;
    }
    __syncthreads();
    m = red[0];
    __syncthreads();

    float e[8];
    e[0] = __expf(v0.x - m); e[1] = __expf(v0.y - m);
    e[2] = __expf(v0.z - m); e[3] = __expf(v0.w - m);
    e[4] = __expf(v1.x - m); e[5] = __expf(v1.y - m);
    e[6] = __expf(v1.z - m); e[7] = __expf(v1.w - m);

    float s = 0.f;
#pragma unroll
    for (int i = 0; i < 8; i++) s += e[i];
#pragma unroll
    for (int o = 16; o; o >>= 1) s += __shfl_xor_sync(0xFFFFFFFFu, s, o);
    if (lane == 0) red[wid] = s;
    __syncthreads();
    if (tid == 0) {
        float ss = 0.f;
#pragma unroll
        for (int i = 0; i < 8; i++) ss += red[i];
        red[0] = ss;
    }
    __syncthreads();
    const float inv = 1.0f / red[0];

    float r0[4] = {e[0] * inv, e[1] * inv, e[2] * inv, e[3] * inv};
    float r1[4] = {e[4] * inv, e[5] * inv, e[6] * inv, e[7] * inv};
    row[tid]       = make_float4(r0[0], r0[1], r0[2], r0[3]);
    row[tid + 256] = make_float4(r1[0], r1[1], r1[2], r1[3]);

    uint2* ah2 = reinterpret_cast<uint2*>(g_ah + rb);
    uint2* al2 = reinterpret_cast<uint2*>(g_al + rb);
#pragma unroll
    for (int half = 0; half < 2; half++) {
        const float* r = half ? r1 : r0;
        __nv_bfloat162 h0 = __floats2bfloat162_rn(r[0], r[1]);
        __nv_bfloat162 h1 = __floats2bfloat162_rn(r[2], r[3]);
        float2 f0 = __bfloat1622float2(h0), f1 = __bfloat1622float2(h1);
        __nv_bfloat162 l0 = __floats2bfloat162_rn(r[0] - f0.x, r[1] - f0.y);
        __nv_bfloat162 l1 = __floats2bfloat162_rn(r[2] - f1.x, r[3] - f1.y);
        const int idx = tid + half * 256;
        ah2[idx] = make_uint2(*reinterpret_cast<uint32_t*>(&h0),
                              *reinterpret_cast<uint32_t*>(&h1));
        al2[idx] = make_uint2(*reinterpret_cast<uint32_t*>(&l0),
                              *reinterpret_cast<uint32_t*>(&l1));
    }
}

// -------------------- launch -------------------------------------------------
extern "C" void kernel_launch(void* const* d_in, const int* in_sizes, int n_in,
                              void* d_out, int out_size) {
    const float* query     = (const float*)d_in[0];
    const float* key       = (const float*)d_in[1];
    const float* value     = (const float*)d_in[2];
    const float* attn_bias = (const float*)d_in[3];
    const float* Wq        = (const float*)d_in[4];
    const float* bq        = (const float*)d_in[5];
    const float* Wk        = (const float*)d_in[6];
    const float* bk        = (const float*)d_in[7];

    float* out  = (float*)d_out;                     // [B,S,D]
    float* attn = out + SZ_BSD;                      // [B,S,S]

    cudaFuncSetAttribute(proj_kernel,   cudaFuncAttributeMaxDynamicSharedMemorySize, GEMM_SMEM_BYTES);
    cudaFuncSetAttribute(scores_kernel, cudaFuncAttributeMaxDynamicSharedMemorySize, GEMM_SMEM_BYTES);
    cudaFuncSetAttribute(pv_kernel,     cudaFuncAttributeMaxDynamicSharedMemorySize, GEMM_SMEM_BYTES);

    const int n4_bsd = (int)(SZ_BSD / 4);
    const int n4_w   = DDIM * DDIM / 4;

    split_kernel<<<n4_bsd / 256, 256>>>(query, 0, n4_bsd);
    split_kernel<<<n4_bsd / 256, 256>>>(key,   1, n4_bsd);
    split_kernel<<<n4_w / 256,   256>>>(Wq,    2, n4_w);
    split_kernel<<<n4_w / 256,   256>>>(Wk,    3, n4_w);
    vsplit_kernel<<<dim3(SDIM / 32, DDIM / 32, BDIM), 256>>>(value);

    proj_kernel<<<dim3(DDIM / 128, BDIM * SDIM / 128, 2), 256, GEMM_SMEM_BYTES>>>(bq, bk);
    scores_kernel<<<dim3(SDIM / 128, SDIM / 128, BDIM), 256, GEMM_SMEM_BYTES>>>(attn_bias, attn);
    softmax_kernel<<<dim3(SDIM, BDIM), 256>>>(attn);
    pv_kernel<<<dim3(DDIM / 128, SDIM / 128, BDIM), 256, GEMM_SMEM_BYTES>>>(out);
}

// round 13
// speedup vs baseline: 1.5659x; 1.0550x over previous
#include <cuda_runtime.h>
#include <cuda_bf16.h>
#include <cstdint>

#define BDIM 16
#define SDIM 2048
#define DDIM 512

#define SZ_BSD ((size_t)BDIM * SDIM * DDIM)   // 16,777,216
#define SZ_BSS ((size_t)BDIM * SDIM * SDIM)   // 67,108,864

// -------------------- device scratch (static, harness-legal) ----------------
__device__ __nv_bfloat16 g_inqh[SZ_BSD], g_inql[SZ_BSD];   // split(query)
__device__ __nv_bfloat16 g_inkh[SZ_BSD], g_inkl[SZ_BSD];   // split(key)
__device__ __nv_bfloat16 g_wh[2 * DDIM * DDIM], g_wl[2 * DDIM * DDIM]; // split(Wq|Wk)
__device__ __nv_bfloat16 g_qh[SZ_BSD], g_ql[SZ_BSD];       // split(q)
__device__ __nv_bfloat16 g_kh[SZ_BSD], g_kl[SZ_BSD];       // split(k)
__device__ __nv_bfloat16 g_vh[SZ_BSD], g_vl[SZ_BSD];       // split(V^T) [b][d][s]
__device__ __nv_bfloat16 g_ah[SZ_BSS], g_al[SZ_BSS];       // split(attention)

// -------------------- GEMM building blocks ----------------------------------
// SMEM tile: 128 rows x 32 bf16, padded row stride 40 elems (80B).
// 80B stride => ldmatrix 8-row groups hit all eight 16B slots mod 128 (no conflicts).
#define ROWB 80
#define BUFB (128 * ROWB)        // 10240 B per half-tensor tile
#define STAGEB (4 * BUFB)        // Ah, Al, Bh, Bl
#define GEMM_SMEM_BYTES (2 * STAGEB)  // 81920 -> 2 CTAs/SM fit in 228KB

__device__ __forceinline__ uint32_t smem_u32(const void* p) {
    return (uint32_t)__cvta_generic_to_shared(p);
}

__device__ __forceinline__ void cp16(uint32_t dst, const void* src) {
    asm volatile("cp.async.cg.shared.global [%0], [%1], 16;" :: "r"(dst), "l"(src));
}
__device__ __forceinline__ void cp_commit() {
    asm volatile("cp.async.commit_group;");
}
template <int N>
__device__ __forceinline__ void cp_wait() {
    asm volatile("cp.async.wait_group %0;" :: "n"(N));
}

__device__ __forceinline__ void ldsm4(uint32_t* r, uint32_t addr) {
    asm volatile("ldmatrix.sync.aligned.m8n8.x4.shared.b16 {%0,%1,%2,%3}, [%4];"
                 : "=r"(r[0]), "=r"(r[1]), "=r"(r[2]), "=r"(r[3]) : "r"(addr));
}

#define MMA(d, a, b)                                                       \
    asm volatile(                                                          \
        "mma.sync.aligned.m16n8k16.row.col.f32.bf16.bf16.f32 "             \
        "{%0,%1,%2,%3},{%4,%5,%6,%7},{%8,%9},{%0,%1,%2,%3};\n"             \
        : "+f"((d)[0]), "+f"((d)[1]), "+f"((d)[2]), "+f"((d)[3])           \
        : "r"((a)[0]), "r"((a)[1]), "r"((a)[2]), "r"((a)[3]),              \
          "r"((b)[0]), "r"((b)[1]))

// Issue cp.async for one stage: {Ah, Al, Bh, Bl}, each 128 rows x 32 cols (64B).
// 2048 16B-chunks, 8 per thread.
__device__ __forceinline__ void issue_stage(
    const __nv_bfloat16* __restrict__ Ah, const __nv_bfloat16* __restrict__ Al, int lda,
    const __nv_bfloat16* __restrict__ Bh, const __nv_bfloat16* __restrict__ Bl, int ldb,
    int k0, uint32_t sstage, int tid) {
    const __nv_bfloat16* srcs[4] = {Ah, Al, Bh, Bl};
    const int lds[4] = {lda, lda, ldb, ldb};
#pragma unroll
    for (int i = 0; i < 8; i++) {
        const int id = tid + i * 256;
        const int buf = id >> 9;
        const int r = (id >> 2) & 127;
        const int c = id & 3;
        cp16(sstage + buf * BUFB + r * ROWB + c * 16,
             srcs[buf] + (size_t)r * lds[buf] + k0 + c * 8);
    }
    cp_commit();
}

// Compute 3-pass (AhBh + AhBl + AlBh) over one 128x128x32 smem stage.
// Interleaved per-mi A loads keep peak live registers ~100 (fits 128-reg cap
// from launch_bounds(256,2) without spills). Per-acc contribution order is
// ah*bh -> ah*bl -> al*bh, identical to the batched form (same numerics).
__device__ __forceinline__ void compute_stage(uint32_t sstage, float acc[4][4][4],
                                              int tid) {
    const int lane = tid & 31, w = tid >> 5;
    const int wm = w & 1, wn = w >> 1;
    // A fragment base (16x16 tile): lanes 0-15 rows, lanes 16-31 k+8 chunk
    const uint32_t aoff = (uint32_t)((wm * 64 + (lane & 15)) * ROWB + ((lane >> 4) << 4));
    // B fragment base (16n x 16k): lanes %8 -> n row, bit4 -> n+8, bit3 -> k+8
    const uint32_t boff = (uint32_t)((wn * 32 + ((lane >> 4) & 1) * 8 + (lane & 7)) * ROWB +
                                     (((lane >> 3) & 1) << 4));
    const uint32_t aH = sstage + aoff, aL = sstage + BUFB + aoff;
    const uint32_t bH = sstage + 2 * BUFB + boff, bL = sstage + 3 * BUFB + boff;

#pragma unroll
    for (int ks = 0; ks < 2; ks++) {           // two k16 halves (byte offset 32)
        const uint32_t k2 = ks * 32;
        uint32_t bh[2][4], bl[2][4];
#pragma unroll
        for (int bi = 0; bi < 2; bi++) ldsm4(bh[bi], bH + bi * 16 * ROWB + k2);
#pragma unroll
        for (int bi = 0; bi < 2; bi++) ldsm4(bl[bi], bL + bi * 16 * ROWB + k2);
#pragma unroll
        for (int mi = 0; mi < 4; mi++) {
            uint32_t af[4];
            ldsm4(af, aH + mi * 16 * ROWB + k2);        // A-hi fragment
#pragma unroll
            for (int ni = 0; ni < 4; ni++)
                MMA(acc[mi][ni], af, &bh[ni >> 1][(ni & 1) * 2]);
#pragma unroll
            for (int ni = 0; ni < 4; ni++)
                MMA(acc[mi][ni], af, &bl[ni >> 1][(ni & 1) * 2]);
            ldsm4(af, aL + mi * 16 * ROWB + k2);        // A-lo fragment (reuses regs)
#pragma unroll
            for (int ni = 0; ni < 4; ni++)
                MMA(acc[mi][ni], af, &bh[ni >> 1][(ni & 1) * 2]);
        }
    }
}

// Full 128x128 GEMM mainloop over K = KT*32, double-buffered cp.async.
__device__ __forceinline__ void gemm_main(
    const __nv_bfloat16* __restrict__ Ah, const __nv_bfloat16* __restrict__ Al, int lda,
    const __nv_bfloat16* __restrict__ Bh, const __nv_bfloat16* __restrict__ Bl, int ldb,
    int KT, float acc[4][4][4]) {
    extern __shared__ char smem[];
    const int tid = threadIdx.x;
    const uint32_t sb = smem_u32(smem);

#pragma unroll
    for (int i = 0; i < 4; i++)
#pragma unroll
        for (int j = 0; j < 4; j++)
#pragma unroll
            for (int c = 0; c < 4; c++) acc[i][j][c] = 0.f;

    issue_stage(Ah, Al, lda, Bh, Bl, ldb, 0, sb, tid);

#pragma unroll 2
    for (int kt = 0; kt < KT; kt++) {
        if (kt + 1 < KT) {
            issue_stage(Ah, Al, lda, Bh, Bl, ldb, (kt + 1) * 32,
                        sb + ((kt + 1) & 1) * STAGEB, tid);
            cp_wait<1>();
        } else {
            cp_wait<0>();
        }
        __syncthreads();
        compute_stage(sb + (kt & 1) * STAGEB, acc, tid);
        __syncthreads();
    }
}

// -------------------- prep kernels ------------------------------------------
// y=0: query->inq, y=1: key->ink
__global__ void __launch_bounds__(256) splitqk_kernel(const float* __restrict__ query,
                                                      const float* __restrict__ key) {
    const int i = blockIdx.x * 256 + threadIdx.x;
    const float* src = blockIdx.y ? key : query;
    __nv_bfloat16* h = blockIdx.y ? g_inkh : g_inqh;
    __nv_bfloat16* l = blockIdx.y ? g_inkl : g_inql;
    const float4 v = reinterpret_cast<const float4*>(src)[i];
    __nv_bfloat162 h0 = __floats2bfloat162_rn(v.x, v.y);
    __nv_bfloat162 h1 = __floats2bfloat162_rn(v.z, v.w);
    float2 f0 = __bfloat1622float2(h0), f1 = __bfloat1622float2(h1);
    __nv_bfloat162 l0 = __floats2bfloat162_rn(v.x - f0.x, v.y - f0.y);
    __nv_bfloat162 l1 = __floats2bfloat162_rn(v.z - f1.x, v.w - f1.y);
    reinterpret_cast<uint2*>(h)[i] =
        make_uint2(*reinterpret_cast<uint32_t*>(&h0), *reinterpret_cast<uint32_t*>(&h1));
    reinterpret_cast<uint2*>(l)[i] =
        make_uint2(*reinterpret_cast<uint32_t*>(&l0), *reinterpret_cast<uint32_t*>(&l1));
}

// y=0: Wq -> w[0], y=1: Wk -> w[1]
__global__ void __launch_bounds__(256) splitw_kernel(const float* __restrict__ Wq,
                                                     const float* __restrict__ Wk) {
    const int i = blockIdx.x * 256 + threadIdx.x;
    const float* src = blockIdx.y ? Wk : Wq;
    __nv_bfloat16* h = g_wh + (size_t)blockIdx.y * DDIM * DDIM;
    __nv_bfloat16* l = g_wl + (size_t)blockIdx.y * DDIM * DDIM;
    const float4 v = reinterpret_cast<const float4*>(src)[i];
    __nv_bfloat162 h0 = __floats2bfloat162_rn(v.x, v.y);
    __nv_bfloat162 h1 = __floats2bfloat162_rn(v.z, v.w);
    float2 f0 = __bfloat1622float2(h0), f1 = __bfloat1622float2(h1);
    __nv_bfloat162 l0 = __floats2bfloat162_rn(v.x - f0.x, v.y - f0.y);
    __nv_bfloat162 l1 = __floats2bfloat162_rn(v.z - f1.x, v.w - f1.y);
    reinterpret_cast<uint2*>(h)[i] =
        make_uint2(*reinterpret_cast<uint32_t*>(&h0), *reinterpret_cast<uint32_t*>(&h1));
    reinterpret_cast<uint2*>(l)[i] =
        make_uint2(*reinterpret_cast<uint32_t*>(&l0), *reinterpret_cast<uint32_t*>(&l1));
}

// value [b][s][d] fp32 -> g_vh/g_vl [b][d][s] bf16 hi/lo (32x32 tiles)
__global__ void __launch_bounds__(256) vsplit_kernel(const float* __restrict__ value) {
    __shared__ float t[32][33];
    const int tid = threadIdx.x;
    const int b = blockIdx.z;
    const size_t s0 = (size_t)blockIdx.x * 32;
    const size_t d0 = (size_t)blockIdx.y * 32;
    const float* src = value + ((size_t)b * SDIM + s0) * DDIM + d0;
#pragma unroll
    for (int p = 0; p < 4; p++) {
        const int idx = tid + p * 256;
        const int r = idx >> 5, c = idx & 31;
        t[r][c] = src[(size_t)r * DDIM + c];
    }
    __syncthreads();
    __nv_bfloat16* dh = g_vh + ((size_t)b * DDIM + d0) * SDIM + s0;
    __nv_bfloat16* dl = g_vl + ((size_t)b * DDIM + d0) * SDIM + s0;
#pragma unroll
    for (int p = 0; p < 4; p++) {
        const int idx = tid + p * 256;
        const int dr = idx >> 5, sc = idx & 31;
        const float x = t[sc][dr];
        const __nv_bfloat16 h = __float2bfloat16(x);
        dh[(size_t)dr * SDIM + sc] = h;
        dl[(size_t)dr * SDIM + sc] = __float2bfloat16(x - __bfloat162float(h));
    }
}

// -------------------- GEMM kernels ------------------------------------------
__global__ void __launch_bounds__(256, 2) proj_kernel(
    const float* __restrict__ bq, const float* __restrict__ bk) {
    const int z = blockIdx.z;
    const size_t row0 = (size_t)blockIdx.y * 128;
    const int col0 = blockIdx.x * 128;
    const __nv_bfloat16* Ah = (z ? g_inkh : g_inqh) + row0 * DDIM;
    const __nv_bfloat16* Al = (z ? g_inkl : g_inql) + row0 * DDIM;
    const __nv_bfloat16* Bh = g_wh + (size_t)z * DDIM * DDIM + (size_t)col0 * DDIM;
    const __nv_bfloat16* Bl = g_wl + (size_t)z * DDIM * DDIM + (size_t)col0 * DDIM;

    float acc[4][4][4];
    gemm_main(Ah, Al, DDIM, Bh, Bl, DDIM, DDIM / 32, acc);

    const int tid = threadIdx.x, lane = tid & 31, w = tid >> 5;
    const int wm = w & 1, wn = w >> 1;
    const int g = lane >> 2, tg = lane & 3;
    const float* bias = z ? bk : bq;
    __nv_bfloat16* oh = z ? g_kh : g_qh;
    __nv_bfloat16* ol = z ? g_kl : g_ql;
#pragma unroll
    for (int mi = 0; mi < 4; mi++) {
#pragma unroll
        for (int ni = 0; ni < 4; ni++) {
            const size_t r = row0 + wm * 64 + mi * 16 + g;
            const int c = col0 + wn * 32 + ni * 8 + tg * 2;
            const float b0 = bias[c], b1 = bias[c + 1];
#pragma unroll
            for (int hh = 0; hh < 2; hh++) {
                const float x = acc[mi][ni][2 * hh]     + b0;
                const float y = acc[mi][ni][2 * hh + 1] + b1;
                __nv_bfloat162 h2 = __floats2bfloat162_rn(x, y);
                float2 hf = __bfloat1622float2(h2);
                __nv_bfloat162 l2 = __floats2bfloat162_rn(x - hf.x, y - hf.y);
                const size_t o = (r + hh * 8) * DDIM + c;
                *reinterpret_cast<uint32_t*>(oh + o) = *reinterpret_cast<uint32_t*>(&h2);
                *reinterpret_cast<uint32_t*>(ol + o) = *reinterpret_cast<uint32_t*>(&l2);
            }
        }
    }
}

__global__ void __launch_bounds__(256, 2) scores_kernel(
    const float* __restrict__ attn_bias, float* __restrict__ attn) {
    const int kt = blockIdx.x, qt = blockIdx.y, b = blockIdx.z;
    const size_t abase = ((size_t)b * SDIM + qt * 128) * DDIM;
    const size_t bbase = ((size_t)b * SDIM + kt * 128) * DDIM;

    float acc[4][4][4];
    gemm_main(g_qh + abase, g_ql + abase, DDIM, g_kh + bbase, g_kl + bbase, DDIM,
              DDIM / 32, acc);

    const int tid = threadIdx.x, lane = tid & 31, w = tid >> 5;
    const int wm = w & 1, wn = w >> 1;
    const int g = lane >> 2, tg = lane & 3;
    float* aout = attn + (size_t)b * SDIM * SDIM;
#pragma unroll
    for (int mi = 0; mi < 4; mi++) {
#pragma unroll
        for (int ni = 0; ni < 4; ni++) {
            const size_t qr = (size_t)qt * 128 + wm * 64 + mi * 16 + g;
            const int kc = kt * 128 + wn * 32 + ni * 8 + tg * 2;
            const float2 bv0 = *reinterpret_cast<const float2*>(&attn_bias[qr * SDIM + kc]);
            const float2 bv1 = *reinterpret_cast<const float2*>(&attn_bias[(qr + 8) * SDIM + kc]);
            *reinterpret_cast<float2*>(&aout[qr * SDIM + kc]) =
                make_float2(acc[mi][ni][0] + bv0.x, acc[mi][ni][1] + bv0.y);
            *reinterpret_cast<float2*>(&aout[(qr + 8) * SDIM + kc]) =
                make_float2(acc[mi][ni][2] + bv1.x, acc[mi][ni][3] + bv1.y);
        }
    }
}

__global__ void __launch_bounds__(256, 2) pv_kernel(float* __restrict__ out) {
    const int dt = blockIdx.x, qt = blockIdx.y, b = blockIdx.z;
    const size_t abase = (size_t)b * SDIM * SDIM + (size_t)qt * 128 * SDIM;
    const size_t bbase = ((size_t)b * DDIM + dt * 128) * SDIM;

    float acc[4][4][4];
    gemm_main(g_ah + abase, g_al + abase, SDIM, g_vh + bbase, g_vl + bbase, SDIM,
              SDIM / 32, acc);

    const int tid = threadIdx.x, lane = tid & 31, w = tid >> 5;
    const int wm = w & 1, wn = w >> 1;
    const int g = lane >> 2, tg = lane & 3;
#pragma unroll
    for (int mi = 0; mi < 4; mi++) {
#pragma unroll
        for (int ni = 0; ni < 4; ni++) {
            const size_t r = (size_t)qt * 128 + wm * 64 + mi * 16 + g;
            const int c = dt * 128 + wn * 32 + ni * 8 + tg * 2;
            const size_t base = ((size_t)b * SDIM + r) * DDIM + c;
            *reinterpret_cast<float2*>(&out[base]) =
                make_float2(acc[mi][ni][0], acc[mi][ni][1]);
            *reinterpret_cast<float2*>(&out[base + 8 * DDIM]) =
                make_float2(acc[mi][ni][2], acc[mi][ni][3]);
        }
    }
}

// -------------------- softmax (in-place) + bf16 hi/lo split write -----------
__global__ void __launch_bounds__(256) softmax_kernel(float* __restrict__ attn) {
    __shared__ float red[8];
    const int tid = threadIdx.x, lane = tid & 31, wid = tid >> 5;
    const size_t rb = ((size_t)blockIdx.y * SDIM + blockIdx.x) * SDIM;
    float4* row = reinterpret_cast<float4*>(attn + rb);

    const float4 v0 = row[tid];
    const float4 v1 = row[tid + 256];

    float m = fmaxf(fmaxf(fmaxf(v0.x, v0.y), fmaxf(v0.z, v0.w)),
                    fmaxf(fmaxf(v1.x, v1.y), fmaxf(v1.z, v1.w)));
#pragma unroll
    for (int o = 16; o; o >>= 1) m = fmaxf(m, __shfl_xor_sync(0xFFFFFFFFu, m, o));
    if (lane == 0) red[wid] = m;
    __syncthreads();
    if (tid == 0) {
        float mm = red[0];
#pragma unroll
        for (int i = 1; i < 8; i++) mm = fmaxf(mm, red[i]);
        red[0] = mm;
    }
    __syncthreads();
    m = red[0];
    __syncthreads();

    float e[8];
    e[0] = __expf(v0.x - m); e[1] = __expf(v0.y - m);
    e[2] = __expf(v0.z - m); e[3] = __expf(v0.w - m);
    e[4] = __expf(v1.x - m); e[5] = __expf(v1.y - m);
    e[6] = __expf(v1.z - m); e[7] = __expf(v1.w - m);

    float s = 0.f;
#pragma unroll
    for (int i = 0; i < 8; i++) s += e[i];
#pragma unroll
    for (int o = 16; o; o >>= 1) s += __shfl_xor_sync(0xFFFFFFFFu, s, o);
    if (lane == 0) red[wid] = s;
    __syncthreads();
    if (tid == 0) {
        float ss = 0.f;
#pragma unroll
        for (int i = 0; i < 8; i++) ss += red[i];
        red[0] = ss;
    }
    __syncthreads();
    const float inv = 1.0f / red[0];

    float r0[4] = {e[0] * inv, e[1] * inv, e[2] * inv, e[3] * inv};
    float r1[4] = {e[4] * inv, e[5] * inv, e[6] * inv, e[7] * inv};
    row[tid]       = make_float4(r0[0], r0[1], r0[2], r0[3]);
    row[tid + 256] = make_float4(r1[0], r1[1], r1[2], r1[3]);

    uint2* ah2 = reinterpret_cast<uint2*>(g_ah + rb);
    uint2* al2 = reinterpret_cast<uint2*>(g_al + rb);
#pragma unroll
    for (int half = 0; half < 2; half++) {
        const float* r = half ? r1 : r0;
        __nv_bfloat162 h0 = __floats2bfloat162_rn(r[0], r[1]);
        __nv_bfloat162 h1 = __floats2bfloat162_rn(r[2], r[3]);
        float2 f0 = __bfloat1622float2(h0), f1 = __bfloat1622float2(h1);
        __nv_bfloat162 l0 = __floats2bfloat162_rn(r[0] - f0.x, r[1] - f0.y);
        __nv_bfloat162 l1 = __floats2bfloat162_rn(r[2] - f1.x, r[3] - f1.y);
        const int idx = tid + half * 256;
        ah2[idx] = make_uint2(*reinterpret_cast<uint32_t*>(&h0),
                              *reinterpret_cast<uint32_t*>(&h1));
        al2[idx] = make_uint2(*reinterpret_cast<uint32_t*>(&l0),
                              *reinterpret_cast<uint32_t*>(&l1));
    }
}

// -------------------- launch -------------------------------------------------
extern "C" void kernel_launch(void* const* d_in, const int* in_sizes, int n_in,
                              void* d_out, int out_size) {
    const float* query     = (const float*)d_in[0];
    const float* key       = (const float*)d_in[1];
    const float* value     = (const float*)d_in[2];
    const float* attn_bias = (const float*)d_in[3];
    const float* Wq        = (const float*)d_in[4];
    const float* bq        = (const float*)d_in[5];
    const float* Wk        = (const float*)d_in[6];
    const float* bk        = (const float*)d_in[7];

    float* out  = (float*)d_out;                     // [B,S,D]
    float* attn = out + SZ_BSD;                      // [B,S,S]

    cudaFuncSetAttribute(proj_kernel,   cudaFuncAttributeMaxDynamicSharedMemorySize, GEMM_SMEM_BYTES);
    cudaFuncSetAttribute(scores_kernel, cudaFuncAttributeMaxDynamicSharedMemorySize, GEMM_SMEM_BYTES);
    cudaFuncSetAttribute(pv_kernel,     cudaFuncAttributeMaxDynamicSharedMemorySize, GEMM_SMEM_BYTES);

    const int n4_bsd = (int)(SZ_BSD / 4);
    const int n4_w   = DDIM * DDIM / 4;

    splitqk_kernel<<<dim3(n4_bsd / 256, 2), 256>>>(query, key);
    splitw_kernel<<<dim3(n4_w / 256, 2), 256>>>(Wq, Wk);
    vsplit_kernel<<<dim3(SDIM / 32, DDIM / 32, BDIM), 256>>>(value);

    proj_kernel<<<dim3(DDIM / 128, BDIM * SDIM / 128, 2), 256, GEMM_SMEM_BYTES>>>(bq, bk);
    scores_kernel<<<dim3(SDIM / 128, SDIM / 128, BDIM), 256, GEMM_SMEM_BYTES>>>(attn_bias, attn);
    softmax_kernel<<<dim3(SDIM, BDIM), 256>>>(attn);
    pv_kernel<<<dim3(DDIM / 128, SDIM / 128, BDIM), 256, GEMM_SMEM_BYTES>>>(out);
}